// round 5
// baseline (speedup 1.0000x reference)
#include <cuda_runtime.h>
#include <cuda_bf16.h>
#include <math.h>
#include <stdint.h>

constexpr int kB   = 64;
constexpr int kIn  = 1024;
constexpr int kOut = 1024;
constexpr int kE   = 8;
constexpr int kH   = 8;

__device__ float g_part[kE * kB * kOut];   // per-expert scaled partials (e<7 only)
__device__ int   g_flag[16];               // per-o-tile arrival counters (self-resetting)

// ---------------------------------------------------------------------------
// helpers
// ---------------------------------------------------------------------------
__device__ __forceinline__ uint32_t smem_u32(const void* p) {
    uint32_t a;
    asm("{ .reg .u64 t; cvta.to.shared.u64 t, %1; cvt.u32.u64 %0, t; }"
        : "=r"(a) : "l"(p));
    return a;
}
__device__ __forceinline__ uint32_t swz(uint32_t off) {   // SW128 (Swizzle<3,4,3>)
    return off ^ ((off >> 3) & 0x70);
}
__device__ __forceinline__ void sts64(uint32_t addr, uint2 v) {
    asm volatile("st.shared.v2.u32 [%0], {%1,%2};" :: "r"(addr), "r"(v.x), "r"(v.y));
}
__device__ __forceinline__ void ldsm4(uint32_t* r, uint32_t addr) {
    asm volatile("ldmatrix.sync.aligned.m8n8.x4.shared.b16 {%0,%1,%2,%3}, [%4];"
                 : "=r"(r[0]), "=r"(r[1]), "=r"(r[2]), "=r"(r[3]) : "r"(addr));
}
__device__ __forceinline__ void mma16816(float* d, const uint32_t* a,
                                         uint32_t b0, uint32_t b1) {
    asm volatile(
        "mma.sync.aligned.m16n8k16.row.col.f32.bf16.bf16.f32 "
        "{%0,%1,%2,%3}, {%4,%5,%6,%7}, {%8,%9}, {%0,%1,%2,%3};"
        : "+f"(d[0]), "+f"(d[1]), "+f"(d[2]), "+f"(d[3])
        : "r"(a[0]), "r"(a[1]), "r"(a[2]), "r"(a[3]), "r"(b0), "r"(b1));
}
__device__ __forceinline__ void split4(float4 f, uint2& h, uint2& l) {
    __nv_bfloat162 h01 = __floats2bfloat162_rn(f.x, f.y);
    __nv_bfloat162 h23 = __floats2bfloat162_rn(f.z, f.w);
    float a0 = __bfloat162float(h01.x), a1 = __bfloat162float(h01.y);
    float a2 = __bfloat162float(h23.x), a3 = __bfloat162float(h23.y);
    __nv_bfloat162 l01 = __floats2bfloat162_rn(f.x - a0, f.y - a1);
    __nv_bfloat162 l23 = __floats2bfloat162_rn(f.z - a2, f.w - a3);
    h = make_uint2(*reinterpret_cast<uint32_t*>(&h01), *reinterpret_cast<uint32_t*>(&h23));
    l = make_uint2(*reinterpret_cast<uint32_t*>(&l01), *reinterpret_cast<uint32_t*>(&l23));
}

// ---------------------------------------------------------------------------
// Fused GEMM (+prep, +cross-CTA reduce). 128 CTAs x 256 thr. Tile m64 x n64,
// KC=64, 3-stage smem pipeline (3 x 32KB), one sync per chunk.
// ---------------------------------------------------------------------------
constexpr int STAGE = 32768;
constexpr int AH = 0, AL = 8192, BH = 16384, BL = 24576;
constexpr int SMEM_TOTAL = 3 * STAGE;      // 98304
constexpr int CS_OFF = 17472;              // after tr (64*68*4 = 17408 B)

__global__ __launch_bounds__(256, 1)
void gemm_kernel(const float* __restrict__ x, const float* __restrict__ w,
                 const float* __restrict__ align_conv,
                 const float* __restrict__ W_ih, const float* __restrict__ b_ih,
                 const float* __restrict__ b_hh, const float* __restrict__ W_att,
                 const float* __restrict__ b_att, float* __restrict__ out) {
    extern __shared__ char smem[];
    const uint32_t sbase = smem_u32(smem);
    const int tid  = threadIdx.x;
    const int lane = tid & 31;
    const int wid  = tid >> 5;
    const int wm   = wid & 1;
    const int wn   = wid >> 1;
    const int m0   = blockIdx.x * 64;
    const int e    = blockIdx.x >> 4;
    const int t    = blockIdx.x & 15;
    const int ob   = t * 64;

    float acc[2][2][4];
    #pragma unroll
    for (int i = 0; i < 2; i++)
        #pragma unroll
        for (int j = 0; j < 2; j++)
            #pragma unroll
            for (int c = 0; c < 4; c++) acc[i][j][c] = 0.f;

    float sx[4] = {0.f, 0.f, 0.f, 0.f};

    const float4* wg = reinterpret_cast<const float4*>(w);
    const float4* xg = reinterpret_cast<const float4*>(x);
    int rw[4], cw[4];
    #pragma unroll
    for (int q = 0; q < 4; q++) { int j = tid + q * 256; rw[q] = j >> 4; cw[q] = j & 15; }
    uint32_t so[4];
    #pragma unroll
    for (int q = 0; q < 4; q++) so[q] = swz((uint32_t)(rw[q] * 128 + cw[q] * 8));

    float4 wr[4], xr[4];

    // ---- prologue: load ch0, STS to buf0, load ch1 into regs ----
    #pragma unroll
    for (int q = 0; q < 4; q++) {
        wr[q] = wg[(m0 + rw[q]) * 256 + cw[q]];
        xr[q] = xg[rw[q] * 256 + cw[q]];
        sx[q] += xr[q].x + xr[q].y + xr[q].z + xr[q].w;
    }
    #pragma unroll
    for (int q = 0; q < 4; q++) {
        uint2 h, l;
        split4(wr[q], h, l);
        sts64(sbase + AH + so[q], h);
        sts64(sbase + AL + so[q], l);
        split4(xr[q], h, l);
        sts64(sbase + BH + so[q], h);
        sts64(sbase + BL + so[q], l);
    }
    #pragma unroll
    for (int q = 0; q < 4; q++) {
        wr[q] = wg[(m0 + rw[q]) * 256 + 16 + cw[q]];
        xr[q] = xg[rw[q] * 256 + 16 + cw[q]];
        sx[q] += xr[q].x + xr[q].y + xr[q].z + xr[q].w;
    }

    for (int ch = 0; ch < 16; ch++) {
        // STS next chunk (regs hold chunk ch+1) to buf (ch+1)%3 — overlaps
        // with the HMMA drain of chunk ch-1; safe with 3 stages.
        if (ch < 15) {
            const uint32_t sn = sbase + (uint32_t)(((ch + 1) % 3) * STAGE);
            #pragma unroll
            for (int q = 0; q < 4; q++) {
                uint2 h, l;
                split4(wr[q], h, l);
                sts64(sn + AH + so[q], h);
                sts64(sn + AL + so[q], l);
                split4(xr[q], h, l);
                sts64(sn + BH + so[q], h);
                sts64(sn + BL + so[q], l);
            }
        }
        if (ch < 14) {
            const int kc = (ch + 2) * 16;
            #pragma unroll
            for (int q = 0; q < 4; q++) {
                wr[q] = wg[(m0 + rw[q]) * 256 + kc + cw[q]];
                xr[q] = xg[rw[q] * 256 + kc + cw[q]];
                sx[q] += xr[q].x + xr[q].y + xr[q].z + xr[q].w;
            }
        }
        __syncthreads();

        const uint32_t sb = sbase + (uint32_t)((ch % 3) * STAGE);
        #pragma unroll
        for (int kk = 0; kk < 4; kk++) {
            const uint32_t kb = kk * 32;
            const uint32_t arow = (uint32_t)(wm * 32 + (lane & 15));
            const uint32_t akb  = kb + ((lane >> 4) << 4);
            uint32_t ah0[4], ah1[4], al0[4], al1[4], bh[4], bl[4];
            ldsm4(ah0, sb + AH + swz(arow * 128 + akb));
            ldsm4(ah1, sb + AH + swz((arow + 16) * 128 + akb));
            ldsm4(al0, sb + AL + swz(arow * 128 + akb));
            ldsm4(al1, sb + AL + swz((arow + 16) * 128 + akb));
            const uint32_t brow = (uint32_t)(wn * 16 + ((lane >> 4) << 3) + (lane & 7));
            const uint32_t bkb  = kb + (((lane >> 3) & 1) << 4);
            ldsm4(bh, sb + BH + swz(brow * 128 + bkb));
            ldsm4(bl, sb + BL + swz(brow * 128 + bkb));

            #pragma unroll
            for (int ni = 0; ni < 2; ni++) {
                mma16816(acc[0][ni], ah0, bh[2 * ni], bh[2 * ni + 1]);
                mma16816(acc[0][ni], ah0, bl[2 * ni], bl[2 * ni + 1]);
                mma16816(acc[0][ni], al0, bh[2 * ni], bh[2 * ni + 1]);
                mma16816(acc[1][ni], ah1, bh[2 * ni], bh[2 * ni + 1]);
                mma16816(acc[1][ni], ah1, bl[2 * ni], bl[2 * ni + 1]);
                mma16816(acc[1][ni], al1, bh[2 * ni], bh[2 * ni + 1]);
            }
        }
    }
    __syncthreads();   // all LDSM reads done; smem is free for the epilogue

    // ---------------- fused prep: c[b, e] for this CTA's expert ----------------
    float* sums = reinterpret_cast<float*>(smem);              // [64][16]
    #pragma unroll
    for (int q = 0; q < 4; q++) sums[rw[q] * 16 + (tid & 15)] = sx[q];
    __syncthreads();

    float* cs = reinterpret_cast<float*>(smem + CS_OFF);       // [64]
    if (tid < 64) {
        float s = 0.f;
        #pragma unroll
        for (int i = 0; i < 16; i++) s += sums[tid * 16 + i];
        const float pm = s * (1.f / (float)kIn);
        float r[kH];
        #pragma unroll
        for (int j = 0; j < kH; j++)
            r[j] = fmaxf(tanhf(fmaf(pm, W_ih[j], b_ih[j] + b_hh[j])), 0.f);
        float logits[kE], mx = -1e30f;
        #pragma unroll
        for (int f = 0; f < kE; f++) {
            float l = b_att[f];
            #pragma unroll
            for (int j = 0; j < kH; j++) l = fmaf(r[j], W_att[f * kH + j], l);
            logits[f] = l;
            mx = fmaxf(mx, l);
        }
        float se = 0.f, att[kE];
        #pragma unroll
        for (int f = 0; f < kE; f++) { att[f] = expf(logits[f] - mx); se += att[f]; }
        const float inv = 1.f / se;
        float c = 0.f;
        #pragma unroll
        for (int f = 0; f < kE; f++) c = fmaf(att[f] * inv, align_conv[f * kE + e], c);
        cs[tid] = c;
    }
    __syncthreads();

    // ---------------- transpose accumulators to [b][o] via smem ----------------
    float* tr = reinterpret_cast<float*>(smem);                // [64 b][68 pad]
    #pragma unroll
    for (int mi = 0; mi < 2; mi++)
        #pragma unroll
        for (int ni = 0; ni < 2; ni++) {
            const int r0 = wm * 32 + mi * 16 + (lane >> 2);
            const int c0 = wn * 16 + ni * 8 + (lane & 3) * 2;
            tr[c0 * 68 + r0]            = acc[mi][ni][0];
            tr[(c0 + 1) * 68 + r0]      = acc[mi][ni][1];
            tr[c0 * 68 + r0 + 8]        = acc[mi][ni][2];
            tr[(c0 + 1) * 68 + r0 + 8]  = acc[mi][ni][3];
        }
    __syncthreads();

    const int b = tid >> 2;
    const float s = cs[b];

    if (e < 7) {
        // producer: store scaled partial, then release-signal the o-tile flag
        #pragma unroll
        for (int it = 0; it < 4; it++) {
            const int o4 = (tid & 3) + it * 4;
            float4 v = *reinterpret_cast<const float4*>(&tr[b * 68 + o4 * 4]);
            v.x *= s; v.y *= s; v.z *= s; v.w *= s;
            *reinterpret_cast<float4*>(
                &g_part[e * (kB * kOut) + b * kOut + ob + o4 * 4]) = v;
        }
        __threadfence();
        __syncthreads();
        if (tid == 0)
            asm volatile("red.release.gpu.global.add.s32 [%0], 1;"
                         :: "l"(&g_flag[t]) : "memory");
    } else {
        // reducer: wait for 7 producers of this o-tile, combine, write d_out
        if (tid == 0) {
            int v;
            do {
                asm volatile("ld.acquire.gpu.global.b32 %0, [%1];"
                             : "=r"(v) : "l"(&g_flag[t]) : "memory");
                if (v != 7) __nanosleep(64);
            } while (v != 7);
            g_flag[t] = 0;   // reset for next graph replay
        }
        __syncthreads();
        __threadfence();

        const float4* gp4 = reinterpret_cast<const float4*>(g_part);
        #pragma unroll
        for (int it = 0; it < 4; it++) {
            const int o4 = (tid & 3) + it * 4;
            float4 v = *reinterpret_cast<const float4*>(&tr[b * 68 + o4 * 4]);
            v.x *= s; v.y *= s; v.z *= s; v.w *= s;
            const int base = (b * kOut + ob) >> 2;
            #pragma unroll
            for (int e2 = 0; e2 < 7; e2++) {
                float4 p = __ldcg(&gp4[e2 * (kB * kOut / 4) + base + o4]);
                v.x += p.x; v.y += p.y; v.z += p.z; v.w += p.w;
            }
            *reinterpret_cast<float4*>(&out[b * kOut + ob + o4 * 4]) = v;
        }
    }
}

// ---------------------------------------------------------------------------
extern "C" void kernel_launch(void* const* d_in, const int* in_sizes, int n_in,
                              void* d_out, int out_size) {
    const float* x          = (const float*)d_in[0];
    const float* weight     = (const float*)d_in[1];
    const float* align_conv = (const float*)d_in[2];
    const float* W_ih       = (const float*)d_in[3];
    // d_in[4] = W_hh — unused (h0 = 0)
    const float* b_ih       = (const float*)d_in[5];
    const float* b_hh       = (const float*)d_in[6];
    const float* W_att      = (const float*)d_in[7];
    const float* b_att      = (const float*)d_in[8];
    float* out = (float*)d_out;

    cudaFuncSetAttribute(gemm_kernel, cudaFuncAttributeMaxDynamicSharedMemorySize,
                         SMEM_TOTAL);

    gemm_kernel<<<128, 256, SMEM_TOTAL>>>(x, weight, align_conv,
                                          W_ih, b_ih, b_hh, W_att, b_att, out);
}

// round 7
// speedup vs baseline: 1.0012x; 1.0012x over previous
#include <cuda_runtime.h>
#include <cuda_bf16.h>
#include <math.h>
#include <stdint.h>

constexpr int kB   = 64;
constexpr int kIn  = 1024;
constexpr int kOut = 1024;
constexpr int kE   = 8;
constexpr int kH   = 8;

__device__ float g_part[kE * kB * kOut];   // per-expert scaled partials (e<7 only)
__device__ int   g_flag[16];               // per-o-tile arrival counters (self-resetting)

// ---------------------------------------------------------------------------
// helpers
// ---------------------------------------------------------------------------
__device__ __forceinline__ uint32_t smem_u32(const void* p) {
    uint32_t a;
    asm("{ .reg .u64 t; cvta.to.shared.u64 t, %1; cvt.u32.u64 %0, t; }"
        : "=r"(a) : "l"(p));
    return a;
}
__device__ __forceinline__ uint32_t swz(uint32_t off) {   // SW128 (Swizzle<3,4,3>)
    return off ^ ((off >> 3) & 0x70);
}
__device__ __forceinline__ void sts64(uint32_t addr, uint2 v) {
    asm volatile("st.shared.v2.u32 [%0], {%1,%2};" :: "r"(addr), "r"(v.x), "r"(v.y));
}
__device__ __forceinline__ void ldsm4(uint32_t* r, uint32_t addr) {
    asm volatile("ldmatrix.sync.aligned.m8n8.x4.shared.b16 {%0,%1,%2,%3}, [%4];"
                 : "=r"(r[0]), "=r"(r[1]), "=r"(r[2]), "=r"(r[3]) : "r"(addr));
}
__device__ __forceinline__ void mma16816(float* d, const uint32_t* a,
                                         uint32_t b0, uint32_t b1) {
    asm volatile(
        "mma.sync.aligned.m16n8k16.row.col.f32.bf16.bf16.f32 "
        "{%0,%1,%2,%3}, {%4,%5,%6,%7}, {%8,%9}, {%0,%1,%2,%3};"
        : "+f"(d[0]), "+f"(d[1]), "+f"(d[2]), "+f"(d[3])
        : "r"(a[0]), "r"(a[1]), "r"(a[2]), "r"(a[3]), "r"(b0), "r"(b1));
}
__device__ __forceinline__ void split4(float4 f, uint2& h, uint2& l) {
    __nv_bfloat162 h01 = __floats2bfloat162_rn(f.x, f.y);
    __nv_bfloat162 h23 = __floats2bfloat162_rn(f.z, f.w);
    float a0 = __bfloat162float(h01.x), a1 = __bfloat162float(h01.y);
    float a2 = __bfloat162float(h23.x), a3 = __bfloat162float(h23.y);
    __nv_bfloat162 l01 = __floats2bfloat162_rn(f.x - a0, f.y - a1);
    __nv_bfloat162 l23 = __floats2bfloat162_rn(f.z - a2, f.w - a3);
    h = make_uint2(*reinterpret_cast<uint32_t*>(&h01), *reinterpret_cast<uint32_t*>(&h23));
    l = make_uint2(*reinterpret_cast<uint32_t*>(&l01), *reinterpret_cast<uint32_t*>(&l23));
}

// ---------------------------------------------------------------------------
// Fused GEMM (+prep, +cross-CTA reduce). 128 CTAs x 512 thr (16 warps).
// CTA tile m64(eo) x n64(b), KC=64, 2-stage smem (2 x 32KB), warp tile m16xn16.
// ---------------------------------------------------------------------------
constexpr int STAGE = 32768;
constexpr int AH = 0, AL = 8192, BH = 16384, BL = 24576;
constexpr int SMEM_TOTAL = 2 * STAGE;      // 65536
constexpr int CS_OFF = 17408;              // right after tr (64*68*4 bytes)

__global__ __launch_bounds__(512, 1)
void gemm_kernel(const float* __restrict__ x, const float* __restrict__ w,
                 const float* __restrict__ align_conv,
                 const float* __restrict__ W_ih, const float* __restrict__ b_ih,
                 const float* __restrict__ b_hh, const float* __restrict__ W_att,
                 const float* __restrict__ b_att, float* __restrict__ out) {
    extern __shared__ char smem[];
    const uint32_t sbase = smem_u32(smem);
    const int tid  = threadIdx.x;
    const int lane = tid & 31;
    const int wid  = tid >> 5;
    const int wm   = wid & 3;        // 4 m-groups of 16 rows
    const int wn   = wid >> 2;       // 4 n-groups of 16 cols
    const int m0   = blockIdx.x * 64;
    const int e    = blockIdx.x >> 4;
    const int t    = blockIdx.x & 15;
    const int ob   = t * 64;

    float acc[2][4];
    #pragma unroll
    for (int j = 0; j < 2; j++)
        #pragma unroll
        for (int c = 0; c < 4; c++) acc[j][c] = 0.f;

    float sx[2] = {0.f, 0.f};

    const float4* wg = reinterpret_cast<const float4*>(w);
    const float4* xg = reinterpret_cast<const float4*>(x);
    int rw[2], cwv;
    cwv = tid & 15;
    #pragma unroll
    for (int q = 0; q < 2; q++) rw[q] = (tid + q * 512) >> 4;
    uint32_t so[2];
    #pragma unroll
    for (int q = 0; q < 2; q++) so[q] = swz((uint32_t)(rw[q] * 128 + cwv * 8));

    float4 wr[2], xr[2];
    #pragma unroll
    for (int q = 0; q < 2; q++) {
        wr[q] = wg[(m0 + rw[q]) * 256 + cwv];
        xr[q] = xg[rw[q] * 256 + cwv];
        sx[q] += xr[q].x + xr[q].y + xr[q].z + xr[q].w;
    }

    for (int ch = 0; ch < 16; ch++) {
        const uint32_t sb = sbase + (uint32_t)((ch & 1) * STAGE);

        // STS current chunk (held in regs) to buf ch%2
        #pragma unroll
        for (int q = 0; q < 2; q++) {
            uint2 h, l;
            split4(wr[q], h, l);
            sts64(sb + AH + so[q], h);
            sts64(sb + AL + so[q], l);
            split4(xr[q], h, l);
            sts64(sb + BH + so[q], h);
            sts64(sb + BL + so[q], l);
        }
        __syncthreads();

        // prefetch next chunk (lands during this chunk's MMA drain)
        if (ch < 15) {
            const int kc = (ch + 1) * 16;
            #pragma unroll
            for (int q = 0; q < 2; q++) {
                wr[q] = wg[(m0 + rw[q]) * 256 + kc + cwv];
                xr[q] = xg[rw[q] * 256 + kc + cwv];
                sx[q] += xr[q].x + xr[q].y + xr[q].z + xr[q].w;
            }
        }

        // 4 k16 steps: 16 LDSM + 24 HMMA per warp per chunk
        #pragma unroll
        for (int kk = 0; kk < 4; kk++) {
            const uint32_t kb = kk * 32;
            const uint32_t arow = (uint32_t)(wm * 16 + (lane & 15));
            const uint32_t akb  = kb + ((lane >> 4) << 4);
            uint32_t ah[4], al[4], bh[4], bl[4];
            ldsm4(ah, sb + AH + swz(arow * 128 + akb));
            ldsm4(al, sb + AL + swz(arow * 128 + akb));
            const uint32_t brow = (uint32_t)(wn * 16 + ((lane >> 4) << 3) + (lane & 7));
            const uint32_t bkb  = kb + (((lane >> 3) & 1) << 4);
            ldsm4(bh, sb + BH + swz(brow * 128 + bkb));
            ldsm4(bl, sb + BL + swz(brow * 128 + bkb));

            #pragma unroll
            for (int ni = 0; ni < 2; ni++) {
                mma16816(acc[ni], ah, bh[2 * ni], bh[2 * ni + 1]);
                mma16816(acc[ni], ah, bl[2 * ni], bl[2 * ni + 1]);
                mma16816(acc[ni], al, bh[2 * ni], bh[2 * ni + 1]);
            }
        }
        __syncthreads();   // all reads of buf ch%2 done before it is rewritten
    }

    // ---------------- fused prep: c[b, e] for this CTA's expert ----------------
    float* sums = reinterpret_cast<float*>(smem);              // [64][16]
    #pragma unroll
    for (int q = 0; q < 2; q++) sums[rw[q] * 16 + cwv] = sx[q];
    __syncthreads();

    float* cs = reinterpret_cast<float*>(smem + CS_OFF);       // [64]
    if (tid < 64) {
        float s = 0.f;
        #pragma unroll
        for (int i = 0; i < 16; i++) s += sums[tid * 16 + i];
        const float pm = s * (1.f / (float)kIn);
        float r[kH];
        #pragma unroll
        for (int j = 0; j < kH; j++)
            r[j] = fmaxf(tanhf(fmaf(pm, W_ih[j], b_ih[j] + b_hh[j])), 0.f);
        float logits[kE], mx = -1e30f;
        #pragma unroll
        for (int f = 0; f < kE; f++) {
            float l = b_att[f];
            #pragma unroll
            for (int j = 0; j < kH; j++) l = fmaf(r[j], W_att[f * kH + j], l);
            logits[f] = l;
            mx = fmaxf(mx, l);
        }
        float se = 0.f, att[kE];
        #pragma unroll
        for (int f = 0; f < kE; f++) { att[f] = expf(logits[f] - mx); se += att[f]; }
        const float inv = 1.f / se;
        float c = 0.f;
        #pragma unroll
        for (int f = 0; f < kE; f++) c = fmaf(att[f] * inv, align_conv[f * kE + e], c);
        cs[tid] = c;
    }
    __syncthreads();

    // ---------------- transpose accumulators to [b][o] via smem ----------------
    float* tr = reinterpret_cast<float*>(smem);                // [64 b][68 pad]
    #pragma unroll
    for (int ni = 0; ni < 2; ni++) {
        const int r0 = wm * 16 + (lane >> 2);
        const int c0 = wn * 16 + ni * 8 + (lane & 3) * 2;
        tr[c0 * 68 + r0]            = acc[ni][0];
        tr[(c0 + 1) * 68 + r0]      = acc[ni][1];
        tr[c0 * 68 + r0 + 8]        = acc[ni][2];
        tr[(c0 + 1) * 68 + r0 + 8]  = acc[ni][3];
    }
    __syncthreads();

    const int b = tid >> 3;          // 8 threads per sample
    const float s = cs[b];

    if (e < 7) {
        // producer: store scaled partial, then release-signal the o-tile flag
        #pragma unroll
        for (int it = 0; it < 2; it++) {
            const int o4 = (tid & 7) + it * 8;
            float4 v = *reinterpret_cast<const float4*>(&tr[b * 68 + o4 * 4]);
            v.x *= s; v.y *= s; v.z *= s; v.w *= s;
            *reinterpret_cast<float4*>(
                &g_part[e * (kB * kOut) + b * kOut + ob + o4 * 4]) = v;
        }
        __threadfence();
        __syncthreads();
        if (tid == 0)
            asm volatile("red.release.gpu.global.add.s32 [%0], 1;"
                         :: "l"(&g_flag[t]) : "memory");
    } else {
        // reducer: wait for 7 producers of this o-tile, combine, write d_out
        if (tid == 0) {
            int v;
            do {
                asm volatile("ld.acquire.gpu.global.b32 %0, [%1];"
                             : "=r"(v) : "l"(&g_flag[t]) : "memory");
                if (v != 7) __nanosleep(64);
            } while (v != 7);
            g_flag[t] = 0;   // reset for next graph replay
        }
        __syncthreads();
        __threadfence();

        const float4* gp4 = reinterpret_cast<const float4*>(g_part);
        #pragma unroll
        for (int it = 0; it < 2; it++) {
            const int o4 = (tid & 7) + it * 8;
            float4 v = *reinterpret_cast<const float4*>(&tr[b * 68 + o4 * 4]);
            v.x *= s; v.y *= s; v.z *= s; v.w *= s;
            const int base = (b * kOut + ob) >> 2;
            #pragma unroll
            for (int e2 = 0; e2 < 7; e2++) {
                float4 p = __ldcg(&gp4[e2 * (kB * kOut / 4) + base + o4]);
                v.x += p.x; v.y += p.y; v.z += p.z; v.w += p.w;
            }
            *reinterpret_cast<float4*>(&out[b * kOut + ob + o4 * 4]) = v;
        }
    }
}

// ---------------------------------------------------------------------------
extern "C" void kernel_launch(void* const* d_in, const int* in_sizes, int n_in,
                              void* d_out, int out_size) {
    const float* x          = (const float*)d_in[0];
    const float* weight     = (const float*)d_in[1];
    const float* align_conv = (const float*)d_in[2];
    const float* W_ih       = (const float*)d_in[3];
    // d_in[4] = W_hh — unused (h0 = 0)
    const float* b_ih       = (const float*)d_in[5];
    const float* b_hh       = (const float*)d_in[6];
    const float* W_att      = (const float*)d_in[7];
    const float* b_att      = (const float*)d_in[8];
    float* out = (float*)d_out;

    cudaFuncSetAttribute(gemm_kernel, cudaFuncAttributeMaxDynamicSharedMemorySize,
                         SMEM_TOTAL);

    gemm_kernel<<<128, 512, SMEM_TOTAL>>>(x, weight, align_conv,
                                          W_ih, b_ih, b_hh, W_att, b_att, out);
}

// round 8
// speedup vs baseline: 1.0106x; 1.0094x over previous
#include <cuda_runtime.h>
#include <cuda_bf16.h>
#include <math.h>
#include <stdint.h>

constexpr int kB   = 64;
constexpr int kIn  = 1024;
constexpr int kOut = 1024;
constexpr int kE   = 8;
constexpr int kH   = 8;

__device__ float g_part[kE * kB * kOut];   // per-expert scaled partials (e<7 only)
__device__ int   g_flag[16];               // per-o-tile arrival counters (self-resetting)

// ---------------------------------------------------------------------------
// helpers
// ---------------------------------------------------------------------------
__device__ __forceinline__ uint32_t smem_u32(const void* p) {
    uint32_t a;
    asm("{ .reg .u64 t; cvta.to.shared.u64 t, %1; cvt.u32.u64 %0, t; }"
        : "=r"(a) : "l"(p));
    return a;
}
__device__ __forceinline__ uint32_t swz(uint32_t off) {   // SW128 (Swizzle<3,4,3>)
    return off ^ ((off >> 3) & 0x70);
}
__device__ __forceinline__ void sts64(uint32_t addr, uint2 v) {
    asm volatile("st.shared.v2.u32 [%0], {%1,%2};" :: "r"(addr), "r"(v.x), "r"(v.y));
}
__device__ __forceinline__ void ldsm4(uint32_t* r, uint32_t addr) {
    asm volatile("ldmatrix.sync.aligned.m8n8.x4.shared.b16 {%0,%1,%2,%3}, [%4];"
                 : "=r"(r[0]), "=r"(r[1]), "=r"(r[2]), "=r"(r[3]) : "r"(addr));
}
__device__ __forceinline__ void mma16816(float* d, const uint32_t* a,
                                         uint32_t b0, uint32_t b1) {
    asm volatile(
        "mma.sync.aligned.m16n8k16.row.col.f32.bf16.bf16.f32 "
        "{%0,%1,%2,%3}, {%4,%5,%6,%7}, {%8,%9}, {%0,%1,%2,%3};"
        : "+f"(d[0]), "+f"(d[1]), "+f"(d[2]), "+f"(d[3])
        : "r"(a[0]), "r"(a[1]), "r"(a[2]), "r"(a[3]), "r"(b0), "r"(b1));
}
__device__ __forceinline__ void split4(float4 f, uint2& h, uint2& l) {
    __nv_bfloat162 h01 = __floats2bfloat162_rn(f.x, f.y);
    __nv_bfloat162 h23 = __floats2bfloat162_rn(f.z, f.w);
    float a0 = __bfloat162float(h01.x), a1 = __bfloat162float(h01.y);
    float a2 = __bfloat162float(h23.x), a3 = __bfloat162float(h23.y);
    __nv_bfloat162 l01 = __floats2bfloat162_rn(f.x - a0, f.y - a1);
    __nv_bfloat162 l23 = __floats2bfloat162_rn(f.z - a2, f.w - a3);
    h = make_uint2(*reinterpret_cast<uint32_t*>(&h01), *reinterpret_cast<uint32_t*>(&h23));
    l = make_uint2(*reinterpret_cast<uint32_t*>(&l01), *reinterpret_cast<uint32_t*>(&l23));
}

// ---------------------------------------------------------------------------
// Fused GEMM (+prep, +cross-CTA reduce). 128 CTAs x 256 thr (8 warps).
// CTA tile m64(eo) x n64(b), KC=64, 2-stage smem, warp tile m32 x n16.
// Accumulators split per term (HH / HL / LH) -> 12 independent HMMA chains.
// ---------------------------------------------------------------------------
constexpr int STAGE = 32768;
constexpr int AH = 0, AL = 8192, BH = 16384, BL = 24576;
constexpr int SMEM_TOTAL = 2 * STAGE;      // 65536
constexpr int CS_OFF = 17408;              // right after tr (64*68*4 bytes)

__global__ __launch_bounds__(256, 1)
void gemm_kernel(const float* __restrict__ x, const float* __restrict__ w,
                 const float* __restrict__ align_conv,
                 const float* __restrict__ W_ih, const float* __restrict__ b_ih,
                 const float* __restrict__ b_hh, const float* __restrict__ W_att,
                 const float* __restrict__ b_att, float* __restrict__ out) {
    extern __shared__ char smem[];
    const uint32_t sbase = smem_u32(smem);
    const int tid  = threadIdx.x;
    const int lane = tid & 31;
    const int wid  = tid >> 5;
    const int wm   = wid & 1;        // m half (32 rows)
    const int wn   = wid >> 1;       // n quarter (16 cols)
    const int m0   = blockIdx.x * 64;
    const int e    = blockIdx.x >> 4;
    const int t    = blockIdx.x & 15;
    const int ob   = t * 64;

    // Per-term accumulator sets: [term][mi][ni][4]
    float acc[3][2][2][4];
    #pragma unroll
    for (int tm = 0; tm < 3; tm++)
        #pragma unroll
        for (int i = 0; i < 2; i++)
            #pragma unroll
            for (int j = 0; j < 2; j++)
                #pragma unroll
                for (int c = 0; c < 4; c++) acc[tm][i][j][c] = 0.f;

    float sx[4] = {0.f, 0.f, 0.f, 0.f};

    const float4* wg = reinterpret_cast<const float4*>(w);
    const float4* xg = reinterpret_cast<const float4*>(x);
    int rw[4], cw[4];
    #pragma unroll
    for (int q = 0; q < 4; q++) { int j = tid + q * 256; rw[q] = j >> 4; cw[q] = j & 15; }
    uint32_t so[4];
    #pragma unroll
    for (int q = 0; q < 4; q++) so[q] = swz((uint32_t)(rw[q] * 128 + cw[q] * 8));

    float4 wr[4], xr[4];
    #pragma unroll
    for (int q = 0; q < 4; q++) {
        wr[q] = wg[(m0 + rw[q]) * 256 + cw[q]];
        xr[q] = xg[rw[q] * 256 + cw[q]];
    }

    for (int ch = 0; ch < 16; ch++) {
        const uint32_t sb = sbase + (uint32_t)((ch & 1) * STAGE);

        // convert + swizzled STS (also fold x row-sums for the fused prep)
        #pragma unroll
        for (int q = 0; q < 4; q++) {
            uint2 h, l;
            split4(wr[q], h, l);
            sts64(sb + AH + so[q], h);
            sts64(sb + AL + so[q], l);
        }
        #pragma unroll
        for (int q = 0; q < 4; q++) {
            sx[q] += xr[q].x + xr[q].y + xr[q].z + xr[q].w;
            uint2 h, l;
            split4(xr[q], h, l);
            sts64(sb + BH + so[q], h);
            sts64(sb + BL + so[q], l);
        }
        __syncthreads();

        if (ch < 15) {
            const int kc = (ch + 1) * 16;
            #pragma unroll
            for (int q = 0; q < 4; q++) {
                wr[q] = wg[(m0 + rw[q]) * 256 + kc + cw[q]];
                xr[q] = xg[rw[q] * 256 + kc + cw[q]];
            }
        }

        // 4 k16 steps: 24 LDSM + 48 HMMA per warp per chunk
        #pragma unroll
        for (int kk = 0; kk < 4; kk++) {
            const uint32_t kb = kk * 32;
            const uint32_t arow = (uint32_t)(wm * 32 + (lane & 15));
            const uint32_t akb  = kb + ((lane >> 4) << 4);
            uint32_t ah0[4], ah1[4], al0[4], al1[4], bh[4], bl[4];
            ldsm4(ah0, sb + AH + swz(arow * 128 + akb));
            ldsm4(ah1, sb + AH + swz((arow + 16) * 128 + akb));
            ldsm4(al0, sb + AL + swz(arow * 128 + akb));
            ldsm4(al1, sb + AL + swz((arow + 16) * 128 + akb));
            const uint32_t brow = (uint32_t)(wn * 16 + ((lane >> 4) << 3) + (lane & 7));
            const uint32_t bkb  = kb + (((lane >> 3) & 1) << 4);
            ldsm4(bh, sb + BH + swz(brow * 128 + bkb));
            ldsm4(bl, sb + BL + swz(brow * 128 + bkb));

            #pragma unroll
            for (int ni = 0; ni < 2; ni++) {
                mma16816(acc[0][0][ni], ah0, bh[2 * ni], bh[2 * ni + 1]);
                mma16816(acc[1][0][ni], ah0, bl[2 * ni], bl[2 * ni + 1]);
                mma16816(acc[2][0][ni], al0, bh[2 * ni], bh[2 * ni + 1]);
                mma16816(acc[0][1][ni], ah1, bh[2 * ni], bh[2 * ni + 1]);
                mma16816(acc[1][1][ni], ah1, bl[2 * ni], bl[2 * ni + 1]);
                mma16816(acc[2][1][ni], al1, bh[2 * ni], bh[2 * ni + 1]);
            }
        }
    }

    // fold the three term sets together
    #pragma unroll
    for (int i = 0; i < 2; i++)
        #pragma unroll
        for (int j = 0; j < 2; j++)
            #pragma unroll
            for (int c = 0; c < 4; c++)
                acc[0][i][j][c] += acc[1][i][j][c] + acc[2][i][j][c];

    // ---------------- fused prep: c[b, e] for this CTA's expert ----------------
    float* sums = reinterpret_cast<float*>(smem);              // [64][16]
    #pragma unroll
    for (int q = 0; q < 4; q++) sums[rw[q] * 16 + (tid & 15)] = sx[q];
    __syncthreads();

    float* cs = reinterpret_cast<float*>(smem + CS_OFF);       // [64]
    if (tid < 64) {
        float s = 0.f;
        #pragma unroll
        for (int i = 0; i < 16; i++) s += sums[tid * 16 + i];
        const float pm = s * (1.f / (float)kIn);
        float r[kH];
        #pragma unroll
        for (int j = 0; j < kH; j++)
            r[j] = fmaxf(tanhf(fmaf(pm, W_ih[j], b_ih[j] + b_hh[j])), 0.f);
        float logits[kE], mx = -1e30f;
        #pragma unroll
        for (int f = 0; f < kE; f++) {
            float l = b_att[f];
            #pragma unroll
            for (int j = 0; j < kH; j++) l = fmaf(r[j], W_att[f * kH + j], l);
            logits[f] = l;
            mx = fmaxf(mx, l);
        }
        float se = 0.f, att[kE];
        #pragma unroll
        for (int f = 0; f < kE; f++) { att[f] = expf(logits[f] - mx); se += att[f]; }
        const float inv = 1.f / se;
        float c = 0.f;
        #pragma unroll
        for (int f = 0; f < kE; f++) c = fmaf(att[f] * inv, align_conv[f * kE + e], c);
        cs[tid] = c;
    }
    __syncthreads();

    // ---------------- transpose accumulators to [b][o] via smem ----------------
    float* tr = reinterpret_cast<float*>(smem);                // [64 b][68 pad]
    #pragma unroll
    for (int mi = 0; mi < 2; mi++)
        #pragma unroll
        for (int ni = 0; ni < 2; ni++) {
            const int r0 = wm * 32 + mi * 16 + (lane >> 2);
            const int c0 = wn * 16 + ni * 8 + (lane & 3) * 2;
            tr[c0 * 68 + r0]            = acc[0][mi][ni][0];
            tr[(c0 + 1) * 68 + r0]      = acc[0][mi][ni][1];
            tr[c0 * 68 + r0 + 8]        = acc[0][mi][ni][2];
            tr[(c0 + 1) * 68 + r0 + 8]  = acc[0][mi][ni][3];
        }
    __syncthreads();

    const int b = tid >> 2;          // 4 threads per sample
    const float s = cs[b];

    if (e < 7) {
        // producer: store scaled partial, then release-signal the o-tile flag
        #pragma unroll
        for (int it = 0; it < 4; it++) {
            const int o4 = (tid & 3) + it * 4;
            float4 v = *reinterpret_cast<const float4*>(&tr[b * 68 + o4 * 4]);
            v.x *= s; v.y *= s; v.z *= s; v.w *= s;
            *reinterpret_cast<float4*>(
                &g_part[e * (kB * kOut) + b * kOut + ob + o4 * 4]) = v;
        }
        __threadfence();
        __syncthreads();
        if (tid == 0)
            asm volatile("red.release.gpu.global.add.s32 [%0], 1;"
                         :: "l"(&g_flag[t]) : "memory");
    } else {
        // reducer: wait for 7 producers of this o-tile, combine, write d_out
        if (tid == 0) {
            int v;
            do {
                asm volatile("ld.acquire.gpu.global.b32 %0, [%1];"
                             : "=r"(v) : "l"(&g_flag[t]) : "memory");
                if (v != 7) __nanosleep(64);
            } while (v != 7);
            g_flag[t] = 0;   // reset for next graph replay
        }
        __syncthreads();
        __threadfence();

        const float4* gp4 = reinterpret_cast<const float4*>(g_part);
        #pragma unroll
        for (int it = 0; it < 4; it++) {
            const int o4 = (tid & 3) + it * 4;
            float4 v = *reinterpret_cast<const float4*>(&tr[b * 68 + o4 * 4]);
            v.x *= s; v.y *= s; v.z *= s; v.w *= s;
            const int base = (b * kOut + ob) >> 2;
            #pragma unroll
            for (int e2 = 0; e2 < 7; e2++) {
                float4 p = __ldcg(&gp4[e2 * (kB * kOut / 4) + base + o4]);
                v.x += p.x; v.y += p.y; v.z += p.z; v.w += p.w;
            }
            *reinterpret_cast<float4*>(&out[b * kOut + ob + o4 * 4]) = v;
        }
    }
}

// ---------------------------------------------------------------------------
extern "C" void kernel_launch(void* const* d_in, const int* in_sizes, int n_in,
                              void* d_out, int out_size) {
    const float* x          = (const float*)d_in[0];
    const float* weight     = (const float*)d_in[1];
    const float* align_conv = (const float*)d_in[2];
    const float* W_ih       = (const float*)d_in[3];
    // d_in[4] = W_hh — unused (h0 = 0)
    const float* b_ih       = (const float*)d_in[5];
    const float* b_hh       = (const float*)d_in[6];
    const float* W_att      = (const float*)d_in[7];
    const float* b_att      = (const float*)d_in[8];
    float* out = (float*)d_out;

    cudaFuncSetAttribute(gemm_kernel, cudaFuncAttributeMaxDynamicSharedMemorySize,
                         SMEM_TOTAL);

    gemm_kernel<<<128, 256, SMEM_TOTAL>>>(x, weight, align_conv,
                                          W_ih, b_ih, b_hh, W_att, b_att, out);
}

// round 9
// speedup vs baseline: 1.0945x; 1.0830x over previous
#include <cuda_runtime.h>
#include <cuda_bf16.h>
#include <math.h>
#include <stdint.h>

constexpr int kB   = 64;
constexpr int kIn  = 1024;
constexpr int kOut = 1024;
constexpr int kE   = 8;
constexpr int kH   = 8;

__device__ float g_part[kE * kB * kOut];   // per-expert scaled partials (e<7 only)
__device__ int   g_flag[16];               // per-o-tile arrival counters (self-resetting)

// ---------------------------------------------------------------------------
// helpers
// ---------------------------------------------------------------------------
__device__ __forceinline__ uint32_t smem_u32(const void* p) {
    uint32_t a;
    asm("{ .reg .u64 t; cvta.to.shared.u64 t, %1; cvt.u32.u64 %0, t; }"
        : "=r"(a) : "l"(p));
    return a;
}
__device__ __forceinline__ uint32_t swz(uint32_t off) {   // SW128 (Swizzle<3,4,3>)
    return off ^ ((off >> 3) & 0x70);
}
__device__ __forceinline__ void sts64(uint32_t addr, uint2 v) {
    asm volatile("st.shared.v2.u32 [%0], {%1,%2};" :: "r"(addr), "r"(v.x), "r"(v.y));
}
__device__ __forceinline__ void ldsm4(uint32_t* r, uint32_t addr) {
    asm volatile("ldmatrix.sync.aligned.m8n8.x4.shared.b16 {%0,%1,%2,%3}, [%4];"
                 : "=r"(r[0]), "=r"(r[1]), "=r"(r[2]), "=r"(r[3]) : "r"(addr));
}
__device__ __forceinline__ void mma16816(float* d, const uint32_t* a,
                                         uint32_t b0, uint32_t b1) {
    asm volatile(
        "mma.sync.aligned.m16n8k16.row.col.f32.bf16.bf16.f32 "
        "{%0,%1,%2,%3}, {%4,%5,%6,%7}, {%8,%9}, {%0,%1,%2,%3};"
        : "+f"(d[0]), "+f"(d[1]), "+f"(d[2]), "+f"(d[3])
        : "r"(a[0]), "r"(a[1]), "r"(a[2]), "r"(a[3]), "r"(b0), "r"(b1));
}
__device__ __forceinline__ void bar_sync(int id, int cnt) {
    asm volatile("bar.sync %0, %1;" :: "r"(id), "r"(cnt) : "memory");
}
__device__ __forceinline__ void bar_arrive(int id, int cnt) {
    asm volatile("bar.arrive %0, %1;" :: "r"(id), "r"(cnt) : "memory");
}
__device__ __forceinline__ void split4(float4 f, uint2& h, uint2& l) {
    __nv_bfloat162 h01 = __floats2bfloat162_rn(f.x, f.y);
    __nv_bfloat162 h23 = __floats2bfloat162_rn(f.z, f.w);
    float a0 = __bfloat162float(h01.x), a1 = __bfloat162float(h01.y);
    float a2 = __bfloat162float(h23.x), a3 = __bfloat162float(h23.y);
    __nv_bfloat162 l01 = __floats2bfloat162_rn(f.x - a0, f.y - a1);
    __nv_bfloat162 l23 = __floats2bfloat162_rn(f.z - a2, f.w - a3);
    h = make_uint2(*reinterpret_cast<uint32_t*>(&h01), *reinterpret_cast<uint32_t*>(&h23));
    l = make_uint2(*reinterpret_cast<uint32_t*>(&l01), *reinterpret_cast<uint32_t*>(&l23));
}

// ---------------------------------------------------------------------------
// Warp-specialized fused GEMM. 128 CTAs x 384 thr.
// Warps 0-7: consumers (LDSM+HMMA, m32 x n16 each). Warps 8-11: producers
// (LDG fp32 -> bf16 hi/lo split -> swizzled STS). 2-stage smem, named barriers:
//   FULL_s  = id 1+s : producers arrive, consumers sync
//   EMPTY_s = id 3+s : consumers arrive, producers sync
// ---------------------------------------------------------------------------
constexpr int STAGE = 32768;
constexpr int AH = 0, AL = 8192, BH = 16384, BL = 24576;
constexpr int SUMS_OFF = 65536;            // [64][16] floats = 4 KB
constexpr int CS_OFF   = 69632;            // [64] floats
constexpr int SMEM_TOTAL = 69888;
constexpr int NT = 384;

__global__ __launch_bounds__(NT, 1)
void gemm_kernel(const float* __restrict__ x, const float* __restrict__ w,
                 const float* __restrict__ align_conv,
                 const float* __restrict__ W_ih, const float* __restrict__ b_ih,
                 const float* __restrict__ b_hh, const float* __restrict__ W_att,
                 const float* __restrict__ b_att, float* __restrict__ out) {
    extern __shared__ char smem[];
    const uint32_t sbase = smem_u32(smem);
    const int tid  = threadIdx.x;
    const int lane = tid & 31;
    const int wid  = tid >> 5;
    const int m0   = blockIdx.x * 64;
    const int e    = blockIdx.x >> 4;
    const int t    = blockIdx.x & 15;
    const int ob   = t * 64;

    float acc[3][2][2][4];

    if (wid < 8) {
        // ================= CONSUMERS =================
        const int wm = wid & 1;
        const int wn = wid >> 1;
        #pragma unroll
        for (int tm = 0; tm < 3; tm++)
            #pragma unroll
            for (int i = 0; i < 2; i++)
                #pragma unroll
                for (int j = 0; j < 2; j++)
                    #pragma unroll
                    for (int c = 0; c < 4; c++) acc[tm][i][j][c] = 0.f;

        const uint32_t arow = (uint32_t)(wm * 32 + (lane & 15));
        const uint32_t abit = ((uint32_t)(lane >> 4)) << 4;
        const uint32_t brow = (uint32_t)(wn * 16 + ((lane >> 4) << 3) + (lane & 7));
        const uint32_t bbit = (((uint32_t)(lane >> 3) & 1)) << 4;

        for (int ch = 0; ch < 16; ch++) {
            bar_sync(1 + (ch & 1), NT);
            const uint32_t sb = sbase + (uint32_t)((ch & 1) * STAGE);
            #pragma unroll
            for (int kk = 0; kk < 4; kk++) {
                const uint32_t kb = kk * 32;
                uint32_t ah0[4], ah1[4], al0[4], al1[4], bh[4], bl[4];
                ldsm4(ah0, sb + AH + swz(arow * 128 + kb + abit));
                ldsm4(ah1, sb + AH + swz((arow + 16) * 128 + kb + abit));
                ldsm4(al0, sb + AL + swz(arow * 128 + kb + abit));
                ldsm4(al1, sb + AL + swz((arow + 16) * 128 + kb + abit));
                ldsm4(bh,  sb + BH + swz(brow * 128 + kb + bbit));
                ldsm4(bl,  sb + BL + swz(brow * 128 + kb + bbit));
                #pragma unroll
                for (int ni = 0; ni < 2; ni++) {
                    mma16816(acc[0][0][ni], ah0, bh[2 * ni], bh[2 * ni + 1]);
                    mma16816(acc[1][0][ni], ah0, bl[2 * ni], bl[2 * ni + 1]);
                    mma16816(acc[2][0][ni], al0, bh[2 * ni], bh[2 * ni + 1]);
                    mma16816(acc[0][1][ni], ah1, bh[2 * ni], bh[2 * ni + 1]);
                    mma16816(acc[1][1][ni], ah1, bl[2 * ni], bl[2 * ni + 1]);
                    mma16816(acc[2][1][ni], al1, bh[2 * ni], bh[2 * ni + 1]);
                }
            }
            bar_arrive(3 + (ch & 1), NT);
        }
        // fold term sets
        #pragma unroll
        for (int i = 0; i < 2; i++)
            #pragma unroll
            for (int j = 0; j < 2; j++)
                #pragma unroll
                for (int c = 0; c < 4; c++)
                    acc[0][i][j][c] += acc[1][i][j][c] + acc[2][i][j][c];
    } else {
        // ================= PRODUCERS =================
        const int p    = tid - 256;            // 0..127
        const int col  = p & 15;               // float4 slot within chunk
        const int rg   = p >> 4;               // row group (8 rows each)
        const float4* wg = reinterpret_cast<const float4*>(w);
        const float4* xg = reinterpret_cast<const float4*>(x);

        uint32_t so[8];
        int wrow[8];
        #pragma unroll
        for (int q = 0; q < 8; q++) {
            const int row = rg * 8 + q;
            wrow[q] = row;
            so[q] = swz((uint32_t)(row * 128 + col * 8));
        }

        float4 wr[8], xr[8];
        float sx[8];
        #pragma unroll
        for (int q = 0; q < 8; q++) {
            wr[q] = wg[(m0 + wrow[q]) * 256 + col];
            xr[q] = xg[wrow[q] * 256 + col];
            sx[q] = xr[q].x + xr[q].y + xr[q].z + xr[q].w;
        }

        for (int ch = 0; ch < 16; ch++) {
            if (ch >= 2) bar_sync(3 + (ch & 1), NT);
            const uint32_t sb = sbase + (uint32_t)((ch & 1) * STAGE);
            #pragma unroll
            for (int q = 0; q < 8; q++) {
                uint2 h, l;
                split4(wr[q], h, l);
                sts64(sb + AH + so[q], h);
                sts64(sb + AL + so[q], l);
            }
            #pragma unroll
            for (int q = 0; q < 8; q++) {
                uint2 h, l;
                split4(xr[q], h, l);
                sts64(sb + BH + so[q], h);
                sts64(sb + BL + so[q], l);
            }
            bar_arrive(1 + (ch & 1), NT);
            if (ch < 15) {
                const int kc = (ch + 1) * 16;
                #pragma unroll
                for (int q = 0; q < 8; q++) {
                    wr[q] = wg[(m0 + wrow[q]) * 256 + kc + col];
                    xr[q] = xg[wrow[q] * 256 + kc + col];
                    sx[q] += xr[q].x + xr[q].y + xr[q].z + xr[q].w;
                }
            }
        }
        // stash x row-sum partials for the fused prep
        float* sums = reinterpret_cast<float*>(smem + SUMS_OFF);   // [64][16]
        #pragma unroll
        for (int q = 0; q < 8; q++) sums[wrow[q] * 16 + col] = sx[q];
    }
    __syncthreads();

    // ---------------- fused prep: c[b, e] for this CTA's expert ----------------
    float* cs = reinterpret_cast<float*>(smem + CS_OFF);           // [64]
    if (tid < 64) {
        const float* sums = reinterpret_cast<const float*>(smem + SUMS_OFF);
        float s = 0.f;
        #pragma unroll
        for (int i = 0; i < 16; i++) s += sums[tid * 16 + i];
        const float pm = s * (1.f / (float)kIn);
        float r[kH];
        #pragma unroll
        for (int j = 0; j < kH; j++)
            r[j] = fmaxf(tanhf(fmaf(pm, W_ih[j], b_ih[j] + b_hh[j])), 0.f);
        float logits[kE], mx = -1e30f;
        #pragma unroll
        for (int f = 0; f < kE; f++) {
            float l = b_att[f];
            #pragma unroll
            for (int j = 0; j < kH; j++) l = fmaf(r[j], W_att[f * kH + j], l);
            logits[f] = l;
            mx = fmaxf(mx, l);
        }
        float se = 0.f, att[kE];
        #pragma unroll
        for (int f = 0; f < kE; f++) { att[f] = expf(logits[f] - mx); se += att[f]; }
        const float inv = 1.f / se;
        float c = 0.f;
        #pragma unroll
        for (int f = 0; f < kE; f++) c = fmaf(att[f] * inv, align_conv[f * kE + e], c);
        cs[tid] = c;
    }
    __syncthreads();

    // ---------------- transpose accumulators to [b][o] via smem ----------------
    float* tr = reinterpret_cast<float*>(smem);                    // [64 b][68 pad]
    if (wid < 8) {
        const int wm = wid & 1;
        const int wn = wid >> 1;
        #pragma unroll
        for (int mi = 0; mi < 2; mi++)
            #pragma unroll
            for (int ni = 0; ni < 2; ni++) {
                const int r0 = wm * 32 + mi * 16 + (lane >> 2);
                const int c0 = wn * 16 + ni * 8 + (lane & 3) * 2;
                tr[c0 * 68 + r0]            = acc[0][mi][ni][0];
                tr[(c0 + 1) * 68 + r0]      = acc[0][mi][ni][1];
                tr[c0 * 68 + r0 + 8]        = acc[0][mi][ni][2];
                tr[(c0 + 1) * 68 + r0 + 8]  = acc[0][mi][ni][3];
            }
    }
    __syncthreads();

    if (e < 7) {
        // producer CTA: store scaled partial, release-signal the o-tile flag
        if (tid < 256) {
            const int b = tid >> 2;
            const float s = cs[b];
            #pragma unroll
            for (int it = 0; it < 4; it++) {
                const int o4 = (tid & 3) + it * 4;
                float4 v = *reinterpret_cast<const float4*>(&tr[b * 68 + o4 * 4]);
                v.x *= s; v.y *= s; v.z *= s; v.w *= s;
                *reinterpret_cast<float4*>(
                    &g_part[e * (kB * kOut) + b * kOut + ob + o4 * 4]) = v;
            }
            __threadfence();
        }
        __syncthreads();
        if (tid == 0)
            asm volatile("red.release.gpu.global.add.s32 [%0], 1;"
                         :: "l"(&g_flag[t]) : "memory");
    } else {
        // reducer CTA: wait for 7 producers of this o-tile, combine, write d_out
        if (tid == 0) {
            int v;
            do {
                asm volatile("ld.acquire.gpu.global.b32 %0, [%1];"
                             : "=r"(v) : "l"(&g_flag[t]) : "memory");
                if (v != 7) __nanosleep(64);
            } while (v != 7);
            g_flag[t] = 0;   // reset for next graph replay
        }
        __syncthreads();
        __threadfence();

        if (tid < 256) {
            const int b = tid >> 2;
            const float s = cs[b];
            const float4* gp4 = reinterpret_cast<const float4*>(g_part);
            #pragma unroll
            for (int it = 0; it < 4; it++) {
                const int o4 = (tid & 3) + it * 4;
                float4 v = *reinterpret_cast<const float4*>(&tr[b * 68 + o4 * 4]);
                v.x *= s; v.y *= s; v.z *= s; v.w *= s;
                const int base = (b * kOut + ob) >> 2;
                #pragma unroll
                for (int e2 = 0; e2 < 7; e2++) {
                    float4 pv = __ldcg(&gp4[e2 * (kB * kOut / 4) + base + o4]);
                    v.x += pv.x; v.y += pv.y; v.z += pv.z; v.w += pv.w;
                }
                *reinterpret_cast<float4*>(&out[b * kOut + ob + o4 * 4]) = v;
            }
        }
    }
}

// ---------------------------------------------------------------------------
extern "C" void kernel_launch(void* const* d_in, const int* in_sizes, int n_in,
                              void* d_out, int out_size) {
    const float* x          = (const float*)d_in[0];
    const float* weight     = (const float*)d_in[1];
    const float* align_conv = (const float*)d_in[2];
    const float* W_ih       = (const float*)d_in[3];
    // d_in[4] = W_hh — unused (h0 = 0)
    const float* b_ih       = (const float*)d_in[5];
    const float* b_hh       = (const float*)d_in[6];
    const float* W_att      = (const float*)d_in[7];
    const float* b_att      = (const float*)d_in[8];
    float* out = (float*)d_out;

    cudaFuncSetAttribute(gemm_kernel, cudaFuncAttributeMaxDynamicSharedMemorySize,
                         SMEM_TOTAL);

    gemm_kernel<<<128, NT, SMEM_TOTAL>>>(x, weight, align_conv,
                                         W_ih, b_ih, b_hh, W_att, b_att, out);
}